// round 15
// baseline (speedup 1.0000x reference)
#include <cuda_runtime.h>
#include <cuda_fp16.h>
#include <math.h>
#include <cstdint>

#define TT 4
#define BB 2
#define TB 8
#define NN 1024
#define CC 256
#define HH 8
#define DD 32
#define CN (CC*NN)        // 262144
#define TBCN (TB*CN)      // 2097152

// ---------------------------------------------------------------------------
// Scratch (static device globals: no allocations allowed)
// ---------------------------------------------------------------------------
__device__ float g_tmp[TBCN];                        // query + query_pos (fp32, residual)
__device__ __align__(16) __half g_x16[TBCN];         // spike(tmp) fp16 (qkv GEMM input)
__device__ __align__(16) __half g_qkv[3*TBCN];       // spiked q,k,v fp16 (TB,C,N)
__device__ __align__(16) __half g_os[TBCN];          // spiked attention output fp16
__device__ __align__(16) __half g_Mp[64*8*1024];     // per-(head,chunk) K^T V partials fp16 (exact)
__device__ __align__(16) __half g_Mh[64*1024];       // reduced M^T hi fp16, [head][d][e]
__device__ __align__(16) __half g_Ml[64*1024];       // reduced M^T lo fp16, [head][d][e]
__device__ __align__(16) __half g_w16h[4*CC*CC];     // BN-folded weights hi
__device__ __align__(16) __half g_w16l[4*CC*CC];     // BN-folded weights lo
__device__ float g_bp[4*CC];                         // BN-folded biases

// MultiSpike_norm4: round(clamp(x,0,4))/4 ; jnp.round = round-half-even = rintf
__device__ __forceinline__ float spikef(float v){
    v = fminf(fmaxf(v, 0.0f), 4.0f);
    return rintf(v) * 0.25f;
}

__device__ __forceinline__ uint32_t pack2(float a, float b){
    __half2 h = __halves2half2(__float2half_rn(a), __float2half_rn(b));
    return *reinterpret_cast<uint32_t*>(&h);
}

__device__ __forceinline__ uint32_t smem_to_u32(const void* p) {
    uint32_t a;
    asm("{ .reg .u64 t; cvta.to.shared.u64 t, %1; cvt.u32.u64 %0, t; }"
        : "=r"(a) : "l"(p));
    return a;
}

// ---------------------------------------------------------------------------
// Warp MMA + async-copy primitives (baseline PTX, works on .target sm_100)
// ---------------------------------------------------------------------------
__device__ __forceinline__ void ldsm_x4(uint32_t* a, uint32_t addr){
    asm volatile("ldmatrix.sync.aligned.m8n8.x4.shared.b16 {%0,%1,%2,%3}, [%4];"
        : "=r"(a[0]),"=r"(a[1]),"=r"(a[2]),"=r"(a[3]) : "r"(addr));
}
__device__ __forceinline__ void ldsm_x2(uint32_t* b, uint32_t addr){
    asm volatile("ldmatrix.sync.aligned.m8n8.x2.shared.b16 {%0,%1}, [%2];"
        : "=r"(b[0]),"=r"(b[1]) : "r"(addr));
}
__device__ __forceinline__ void ldsm_x2_trans(uint32_t* b, uint32_t addr){
    asm volatile("ldmatrix.sync.aligned.m8n8.x2.trans.shared.b16 {%0,%1}, [%2];"
        : "=r"(b[0]),"=r"(b[1]) : "r"(addr));
}
__device__ __forceinline__ void mma16816(float* d, const uint32_t* a, const uint32_t* b){
    asm volatile("mma.sync.aligned.m16n8k16.row.col.f32.f16.f16.f32 "
        "{%0,%1,%2,%3}, {%4,%5,%6,%7}, {%8,%9}, {%0,%1,%2,%3};"
        : "+f"(d[0]),"+f"(d[1]),"+f"(d[2]),"+f"(d[3])
        : "r"(a[0]),"r"(a[1]),"r"(a[2]),"r"(a[3]), "r"(b[0]),"r"(b[1]));
}
__device__ __forceinline__ void cp_async16(uint32_t smem_addr, const void* gptr){
    asm volatile("cp.async.cg.shared.global [%0], [%1], 16;"
        :: "r"(smem_addr), "l"(gptr));
}
#define CP_COMMIT() asm volatile("cp.async.commit_group;" ::: "memory")
#define CP_WAIT0()  asm volatile("cp.async.wait_group 0;"  ::: "memory")

// ---------------------------------------------------------------------------
// prep (+ merged weight fold):
//   all 2048 CTAs: tmp = q + qp (fp32); x16 = spike(tmp) fp16.
//   CTAs 0..1023 additionally fold one weight element per thread.
// ---------------------------------------------------------------------------
__global__ void prep_kernel(const float4* __restrict__ q, const float4* __restrict__ qp,
                            const float* __restrict__ w,
                            const float* __restrict__ b,
                            const float* __restrict__ gam,
                            const float* __restrict__ beta,
                            const float* __restrict__ mean,
                            const float* __restrict__ var)
{
    int i = blockIdx.x * blockDim.x + threadIdx.x;     // TBCN/4 threads
    float4 a = q[i], c = qp[i];
    float4 s = make_float4(a.x + c.x, a.y + c.y, a.z + c.z, a.w + c.w);
    reinterpret_cast<float4*>(g_tmp)[i] = s;
    uint2 hv = make_uint2(pack2(spikef(s.x), spikef(s.y)),
                          pack2(spikef(s.z), spikef(s.w)));
    reinterpret_cast<uint2*>(g_x16)[i] = hv;

    if (i < 4*CC*CC){
        int oc = i >> 8;                               // i*C + o
        float inv = gam[oc] * rsqrtf(var[oc] + 1e-5f);
        float wp = w[i] * inv;
        __half hi = __float2half_rn(wp);
        __half lo = __float2half_rn(wp - __half2float(hi));
        g_w16h[i] = hi;
        g_w16l[i] = lo;
        if (i < 4*CC){
            float invb = gam[i] * rsqrtf(var[i] + 1e-5f);
            g_bp[i] = (b[i] - mean[i]) * invb + beta[i];
        }
    }
}

// ---------------------------------------------------------------------------
// HMMA GEMM with cp.async double-buffered k-chunk pipeline.
// Per CTA: D[m=128, n=128] = sum_k (Whi+Wlo)[m,k] * X[k,n].
// MODE 0: qkv (src g_x16, M=768, out g_qkv fp16 split by branch, spike)
// MODE 1: proj (src g_os,  M=256, out fp32 = D + bias + residual g_tmp)
// ---------------------------------------------------------------------------
#define AS_STRIDE 72                     // halves per A row (144B: 16-aligned, %128=16)
#define BS_STRIDE 136                    // halves per B row (272B)
#define AS_HALVES (2*128*AS_STRIDE)      // 18432 halves (both planes)
#define STG_HALVES (AS_HALVES + 64*BS_STRIDE)   // 27136 halves = 54272 B per stage
#define GEMM_SMEM (2*STG_HALVES*2)       // 108544 B (2 stages)

template<int MODE>
__global__ void __launch_bounds__(256, 2) mma_gemm_kernel(float* __restrict__ out)
{
    extern __shared__ __half smem[];
    const int tid  = threadIdx.x;
    const int wid  = tid >> 5;
    const int lane = tid & 31;
    const int tb = blockIdx.z;
    const int bn = blockIdx.x * 128;
    const int bm = blockIdx.y * 128;
    const int WOFF = (MODE == 0) ? 0 : 768;
    const int wm = (wid & 1) * 64;              // warp m offset
    const int wn = (wid >> 1) * 32;             // warp n offset

    const __half* xsrc   = (MODE == 0 ? g_x16 : g_os) + tb*CN + bn;
    const __half* wsrc_h = g_w16h + (WOFF + bm)*CC;
    const __half* wsrc_l = g_w16l + (WOFF + bm)*CC;

    float acc[16][4];
#pragma unroll
    for (int i = 0; i < 16; i++)
#pragma unroll
        for (int j = 0; j < 4; j++) acc[i][j] = 0.f;

    // ---- async stage issue: A (both planes) + B for k-chunk kt ----
    auto issue = [&](int kt){
        __half* As = smem + (kt & 1)*STG_HALVES;
        __half* Bs = As + AS_HALVES;
        const int k0 = kt * 64;
#pragma unroll
        for (int j = 0; j < 4; j++){
            int idx = tid + 256*j;              // 0..1023
            int r = idx >> 3;                   // m row 0..127
            int c8 = (idx & 7) << 3;            // k offset
            cp_async16(smem_to_u32(&As[r*AS_STRIDE + c8]),        wsrc_h + r*CC + k0 + c8);
            cp_async16(smem_to_u32(&As[(128 + r)*AS_STRIDE + c8]), wsrc_l + r*CC + k0 + c8);
        }
#pragma unroll
        for (int j = 0; j < 4; j++){
            int idx = tid + 256*j;              // 0..1023
            int r = idx >> 4;                   // k row 0..63
            int c8 = (idx & 15) << 3;           // n offset
            cp_async16(smem_to_u32(&Bs[r*BS_STRIDE + c8]), xsrc + (k0 + r)*NN + c8);
        }
        CP_COMMIT();
    };

    issue(0);
    for (int kt = 0; kt < 4; kt++){
        CP_WAIT0();                 // stage kt transfers complete
        __syncthreads();            // visibility + all warps done with stage kt-1 compute
        if (kt < 3) issue(kt + 1);  // overlaps with compute below
        __half* As = smem + (kt & 1)*STG_HALVES;
        __half* Bs = As + AS_HALVES;
#pragma unroll
        for (int kk = 0; kk < 64; kk += 16){
            uint32_t bf[4][2];
#pragma unroll
            for (int nt = 0; nt < 4; nt++){
                uint32_t addr = smem_to_u32(
                    &Bs[(kk + (lane & 15))*BS_STRIDE + wn + nt*8]);
                ldsm_x2_trans(bf[nt], addr);
            }
#pragma unroll
            for (int mt = 0; mt < 4; mt++){
#pragma unroll
                for (int p = 0; p < 2; p++){
                    uint32_t af[4];
                    uint32_t addr = smem_to_u32(
                        &As[(p*128 + wm + mt*16 + (lane & 15))*AS_STRIDE
                            + kk + (lane >> 4)*8]);
                    ldsm_x4(af, addr);
#pragma unroll
                    for (int nt = 0; nt < 4; nt++)
                        mma16816(acc[mt*4 + nt], af, bf[nt]);
                }
            }
        }
    }

    // ---- epilogue ----
#pragma unroll
    for (int mt = 0; mt < 4; mt++){
#pragma unroll
        for (int nt = 0; nt < 4; nt++){
            const float* a = acc[mt*4 + nt];
            int row = wm + mt*16 + (lane >> 2);      // 0..127 (and +8)
            int col = wn + nt*8 + ((lane & 3) << 1); // 0..126, even
            if (MODE == 0){
                int gm0 = bm + row, gm1 = gm0 + 8;
                float b0 = g_bp[gm0], b1 = g_bp[gm1];
                uint32_t v0 = pack2(spikef(a[0] + b0), spikef(a[1] + b0));
                uint32_t v1 = pack2(spikef(a[2] + b1), spikef(a[3] + b1));
                *reinterpret_cast<uint32_t*>(
                    &g_qkv[(gm0 >> 8)*TBCN + tb*CN + (gm0 & 255)*NN + bn + col]) = v0;
                *reinterpret_cast<uint32_t*>(
                    &g_qkv[(gm1 >> 8)*TBCN + tb*CN + (gm1 & 255)*NN + bn + col]) = v1;
            } else {
                int gm0 = bm + row, gm1 = gm0 + 8;
                float b0 = g_bp[768 + gm0], b1 = g_bp[768 + gm1];
                int i0 = tb*CN + gm0*NN + bn + col;
                int i1 = tb*CN + gm1*NN + bn + col;
                float2 r0 = *reinterpret_cast<const float2*>(&g_tmp[i0]);
                float2 r1 = *reinterpret_cast<const float2*>(&g_tmp[i1]);
                float2 v0 = make_float2(a[0] + b0 + r0.x, a[1] + b0 + r0.y);
                float2 v1 = make_float2(a[2] + b1 + r1.x, a[3] + b1 + r1.y);
                *reinterpret_cast<float2*>(&out[i0]) = v0;
                *reinterpret_cast<float2*>(&out[i1]) = v1;
            }
        }
    }
}

// ---------------------------------------------------------------------------
// Attention phase 1 (HMMA, n-split): partial M[e,d] over one 128-n chunk.
// grid 512 = 64 heads x 8 chunks. Cross-warp smem reduce, then PLAIN fp16
// stores into g_Mp[hh][chunk] — exact (partials are multiples of 1/16, <=128,
// ulp(fp16)@[64,128) = 1/16). No atomics.
// ---------------------------------------------------------------------------
#define KV_STRIDE 136
__global__ void __launch_bounds__(256) kv_kernel()
{
    __shared__ __align__(16) char sbuf[32768];
    __half (*Ks)[KV_STRIDE] = reinterpret_cast<__half(*)[KV_STRIDE]>(sbuf);
    __half (*Vs)[KV_STRIDE] = reinterpret_cast<__half(*)[KV_STRIDE]>(sbuf + 32*KV_STRIDE*2);
    float (*red)[1024] = reinterpret_cast<float(*)[1024]>(sbuf);   // aliases Ks/Vs

    const int hh = blockIdx.x >> 3;              // 0..63
    const int ch = blockIdx.x & 7;               // chunk 0..7
    const int nb = ch << 7;                      // n chunk base
    const int tid = threadIdx.x;
    const int wid = tid >> 5;
    const int lane = tid & 31;
    const __half* K = g_qkv + TBCN   + hh*DD*NN;
    const __half* V = g_qkv + 2*TBCN + hh*DD*NN;

    // load K,V 32 x 128 chunk
#pragma unroll
    for (int j = 0; j < 2; j++){
        int idx = tid + 256*j;                   // 0..511
        int r = idx >> 4;                        // row 0..31
        int c8 = (idx & 15) << 3;                // 0..120
        *reinterpret_cast<uint4*>(&Ks[r][c8]) =
            *reinterpret_cast<const uint4*>(&K[r*NN + nb + c8]);
        *reinterpret_cast<uint4*>(&Vs[r][c8]) =
            *reinterpret_cast<const uint4*>(&V[r*NN + nb + c8]);
    }
    __syncthreads();

    float acc[2][4][4];
#pragma unroll
    for (int mt = 0; mt < 2; mt++)
#pragma unroll
        for (int nt = 0; nt < 4; nt++)
#pragma unroll
            for (int i = 0; i < 4; i++) acc[mt][nt][i] = 0.f;

    const int kslice = wid * 16;
    uint32_t a0[4], a1[4];
    ldsm_x4(a0, smem_to_u32(&Ks[lane & 15][kslice + (lane >> 4)*8]));
    ldsm_x4(a1, smem_to_u32(&Ks[16 + (lane & 15)][kslice + (lane >> 4)*8]));
#pragma unroll
    for (int nt = 0; nt < 4; nt++){
        uint32_t bf[2];
        ldsm_x2(bf, smem_to_u32(&Vs[nt*8 + (lane & 7)][kslice + ((lane >> 3) & 1)*8]));
        mma16816(acc[0][nt], a0, bf);
        mma16816(acc[1][nt], a1, bf);
    }
    __syncthreads();

    // ---- cross-warp reduction (red aliases Ks/Vs) ----
#pragma unroll
    for (int mt = 0; mt < 2; mt++)
#pragma unroll
        for (int nt = 0; nt < 4; nt++)
#pragma unroll
            for (int i = 0; i < 4; i++){
                int e = mt*16 + (lane >> 2) + ((i >= 2) ? 8 : 0);
                int d = nt*8 + ((lane & 3) << 1) + (i & 1);
                red[wid][e*32 + d] = acc[mt][nt][i];
            }
    __syncthreads();
    // 1024 sums, 4 per thread, coalesced; exact fp16 partial store
#pragma unroll
    for (int i = 0; i < 4; i++){
        int j = tid + i*256;                     // covers 0..1023, all indices
        float s = red[0][j] + red[1][j] + red[2][j] + red[3][j]
                + red[4][j] + red[5][j] + red[6][j] + red[7][j];
        g_Mp[(hh*8 + ch)*1024 + j] = __float2half_rn(s);    // exact
    }
}

// ---------------------------------------------------------------------------
// M reduce: per head, sum the 8 fp16 chunk partials (exact in fp32), split
// into exact fp16 hi/lo, store TRANSPOSED [d][e]. grid 64 x 256.
// ---------------------------------------------------------------------------
__global__ void __launch_bounds__(256) mreduce_kernel()
{
    const int hh = blockIdx.x;
    const int tid = threadIdx.x;
#pragma unroll
    for (int o = tid; o < 1024; o += 256){       // o = d*32 + e (output layout)
        int d = o >> 5, e = o & 31;
        const __half* mp = g_Mp + hh*8192 + e*32 + d;
        float s = 0.f;
#pragma unroll
        for (int c = 0; c < 8; c++) s += __half2float(mp[c*1024]);
        __half hi = __float2half_rn(s);
        g_Mh[hh*1024 + o] = hi;
        g_Ml[hh*1024 + o] = __float2half_rn(s - __half2float(hi));
    }
}

// ---------------------------------------------------------------------------
// Attention phase 2 (HMMA, n-split): O[d,n] = spike(0.1*sum_e M[e,d]*Q[e,n]).
// grid 512 = 64 heads x 8 x 128-n chunks. Mh/Ml preloaded from mreduce.
// A = M^T hi/lo, B = Q (trans ldsm). 8 warps x 16-n windows.
// ---------------------------------------------------------------------------
#define QS_STRIDE 136
__global__ void __launch_bounds__(256) qm_kernel()
{
    __shared__ __align__(16) __half Qs[32][QS_STRIDE];
    __shared__ __align__(16) __half Mh[32][40];
    __shared__ __align__(16) __half Ml[32][40];
    const int hh = blockIdx.x >> 3;
    const int nb = (blockIdx.x & 7) << 7;        // 128-n chunk base
    const int tid = threadIdx.x;
    const int wid = tid >> 5;
    const int lane = tid & 31;
    const int cbase = hh * (DD*NN);
    const __half* Q = g_qkv + cbase;

    // copy reduced hi/lo M^T tiles ([d][e] layout already; coalesced)
#pragma unroll
    for (int i = tid; i < 1024; i += 256){
        int d = i >> 5, e = i & 31;
        Mh[d][e] = g_Mh[hh*1024 + i];
        Ml[d][e] = g_Ml[hh*1024 + i];
    }
    // load Q chunk [32 e][128 n]
#pragma unroll
    for (int j = 0; j < 2; j++){
        int idx = tid + 256*j;                   // 0..511
        int r = idx >> 4;                        // e row 0..31
        int c8 = (idx & 15) << 3;                // 0..120
        *reinterpret_cast<uint4*>(&Qs[r][c8]) =
            *reinterpret_cast<const uint4*>(&Q[r*NN + nb + c8]);
    }
    __syncthreads();

    const int wn = wid * 16;
    float acc[2][2][4];
#pragma unroll
    for (int mt = 0; mt < 2; mt++)
#pragma unroll
        for (int nt = 0; nt < 2; nt++)
#pragma unroll
            for (int i = 0; i < 4; i++) acc[mt][nt][i] = 0.f;

#pragma unroll
    for (int e0 = 0; e0 < 32; e0 += 16){
        uint32_t bf[2][2];
#pragma unroll
        for (int nt = 0; nt < 2; nt++)
            ldsm_x2_trans(bf[nt],
                smem_to_u32(&Qs[e0 + (lane & 15)][wn + nt*8]));
#pragma unroll
        for (int mt = 0; mt < 2; mt++){
            uint32_t ah[4], al[4];
            ldsm_x4(ah, smem_to_u32(&Mh[mt*16 + (lane & 15)][e0 + (lane >> 4)*8]));
            ldsm_x4(al, smem_to_u32(&Ml[mt*16 + (lane & 15)][e0 + (lane >> 4)*8]));
#pragma unroll
            for (int nt = 0; nt < 2; nt++){
                mma16816(acc[mt][nt], ah, bf[nt]);
                mma16816(acc[mt][nt], al, bf[nt]);
            }
        }
    }

    // epilogue: spike(0.1*O) -> g_os fp16
#pragma unroll
    for (int mt = 0; mt < 2; mt++){
#pragma unroll
        for (int nt = 0; nt < 2; nt++){
            const float* a = acc[mt][nt];
            int d0 = mt*16 + (lane >> 2);
            int n  = nb + wn + nt*8 + ((lane & 3) << 1);
            uint32_t v0 = pack2(spikef(0.1f*a[0]), spikef(0.1f*a[1]));
            uint32_t v1 = pack2(spikef(0.1f*a[2]), spikef(0.1f*a[3]));
            *reinterpret_cast<uint32_t*>(&g_os[cbase + d0*NN + n]) = v0;
            *reinterpret_cast<uint32_t*>(&g_os[cbase + (d0+8)*NN + n]) = v1;
        }
    }
}

// ---------------------------------------------------------------------------
extern "C" void kernel_launch(void* const* d_in, const int* in_sizes, int n_in,
                              void* d_out, int out_size)
{
    const float* q    = (const float*)d_in[0];
    // d_in[1] (key) and d_in[2] (value) are unused by the reference
    const float* qp   = (const float*)d_in[3];
    const float* w    = (const float*)d_in[4];
    const float* b    = (const float*)d_in[5];
    const float* gam  = (const float*)d_in[6];
    const float* bet  = (const float*)d_in[7];
    const float* mean = (const float*)d_in[8];
    const float* var  = (const float*)d_in[9];
    float* out = (float*)d_out;

    cudaFuncSetAttribute(mma_gemm_kernel<0>,
                         cudaFuncAttributeMaxDynamicSharedMemorySize, GEMM_SMEM);
    cudaFuncSetAttribute(mma_gemm_kernel<1>,
                         cudaFuncAttributeMaxDynamicSharedMemorySize, GEMM_SMEM);

    prep_kernel<<<(TBCN/4)/256, 256>>>((const float4*)q, (const float4*)qp,
                                       w, b, gam, bet, mean, var);

    dim3 gq(NN/128, 768/128, TB);   // 8 x 6 x 8 = 384 CTAs
    mma_gemm_kernel<0><<<gq, 256, GEMM_SMEM>>>(nullptr);

    kv_kernel<<<512, 256>>>();
    mreduce_kernel<<<64, 256>>>();
    qm_kernel<<<512, 256>>>();

    dim3 gp(NN/128, CC/128, TB);    // 8 x 2 x 8 = 128 CTAs
    mma_gemm_kernel<1><<<gp, 256, GEMM_SMEM>>>(out);
}

// round 16
// speedup vs baseline: 1.0121x; 1.0121x over previous
#include <cuda_runtime.h>
#include <cuda_fp16.h>
#include <math.h>
#include <cstdint>

#define TT 4
#define BB 2
#define TB 8
#define NN 1024
#define CC 256
#define HH 8
#define DD 32
#define CN (CC*NN)        // 262144
#define TBCN (TB*CN)      // 2097152

// ---------------------------------------------------------------------------
// Scratch (static device globals: no allocations allowed)
// ---------------------------------------------------------------------------
__device__ float g_tmp[TBCN];                        // query + query_pos (fp32, residual)
__device__ __align__(16) __half g_x16[TBCN];         // spike(tmp) fp16 (qkv GEMM input)
__device__ __align__(16) __half g_qkv[3*TBCN];       // spiked q,k,v fp16 (TB,C,N)
__device__ __align__(16) __half g_os[TBCN];          // spiked attention output fp16
__device__ __align__(16) __half g_Mp[64*8*1024];     // per-(head,chunk) K^T V partials fp16 (exact)
__device__ __align__(16) __half g_Mh[64*1024];       // reduced M^T hi fp16, [head][d][e]
__device__ __align__(16) __half g_Ml[64*1024];       // reduced M^T lo fp16, [head][d][e]
__device__ __align__(16) __half g_w16h[4*CC*CC];     // BN-folded weights hi
__device__ __align__(16) __half g_w16l[4*CC*CC];     // BN-folded weights lo
__device__ float g_bp[4*CC];                         // BN-folded biases

// MultiSpike_norm4: round(clamp(x,0,4))/4 ; jnp.round = round-half-even = rintf
__device__ __forceinline__ float spikef(float v){
    v = fminf(fmaxf(v, 0.0f), 4.0f);
    return rintf(v) * 0.25f;
}

__device__ __forceinline__ uint32_t pack2(float a, float b){
    __half2 h = __halves2half2(__float2half_rn(a), __float2half_rn(b));
    return *reinterpret_cast<uint32_t*>(&h);
}

__device__ __forceinline__ uint32_t smem_to_u32(const void* p) {
    uint32_t a;
    asm("{ .reg .u64 t; cvta.to.shared.u64 t, %1; cvt.u32.u64 %0, t; }"
        : "=r"(a) : "l"(p));
    return a;
}

// ---------------------------------------------------------------------------
// Warp MMA + async-copy primitives (baseline PTX, works on .target sm_100)
// ---------------------------------------------------------------------------
__device__ __forceinline__ void ldsm_x4(uint32_t* a, uint32_t addr){
    asm volatile("ldmatrix.sync.aligned.m8n8.x4.shared.b16 {%0,%1,%2,%3}, [%4];"
        : "=r"(a[0]),"=r"(a[1]),"=r"(a[2]),"=r"(a[3]) : "r"(addr));
}
__device__ __forceinline__ void ldsm_x2(uint32_t* b, uint32_t addr){
    asm volatile("ldmatrix.sync.aligned.m8n8.x2.shared.b16 {%0,%1}, [%2];"
        : "=r"(b[0]),"=r"(b[1]) : "r"(addr));
}
__device__ __forceinline__ void ldsm_x2_trans(uint32_t* b, uint32_t addr){
    asm volatile("ldmatrix.sync.aligned.m8n8.x2.trans.shared.b16 {%0,%1}, [%2];"
        : "=r"(b[0]),"=r"(b[1]) : "r"(addr));
}
__device__ __forceinline__ void mma16816(float* d, const uint32_t* a, const uint32_t* b){
    asm volatile("mma.sync.aligned.m16n8k16.row.col.f32.f16.f16.f32 "
        "{%0,%1,%2,%3}, {%4,%5,%6,%7}, {%8,%9}, {%0,%1,%2,%3};"
        : "+f"(d[0]),"+f"(d[1]),"+f"(d[2]),"+f"(d[3])
        : "r"(a[0]),"r"(a[1]),"r"(a[2]),"r"(a[3]), "r"(b[0]),"r"(b[1]));
}
__device__ __forceinline__ void cp_async16(uint32_t smem_addr, const void* gptr){
    asm volatile("cp.async.cg.shared.global [%0], [%1], 16;"
        :: "r"(smem_addr), "l"(gptr));
}
#define CP_COMMIT() asm volatile("cp.async.commit_group;" ::: "memory")
#define CP_WAIT0()  asm volatile("cp.async.wait_group 0;"  ::: "memory")

// ---------------------------------------------------------------------------
// prep (+ merged weight fold):
//   all 2048 CTAs: tmp = q + qp (fp32); x16 = spike(tmp) fp16.
//   CTAs 0..1023 additionally fold one weight element per thread.
// ---------------------------------------------------------------------------
__global__ void prep_kernel(const float4* __restrict__ q, const float4* __restrict__ qp,
                            const float* __restrict__ w,
                            const float* __restrict__ b,
                            const float* __restrict__ gam,
                            const float* __restrict__ beta,
                            const float* __restrict__ mean,
                            const float* __restrict__ var)
{
    int i = blockIdx.x * blockDim.x + threadIdx.x;     // TBCN/4 threads
    float4 a = q[i], c = qp[i];
    float4 s = make_float4(a.x + c.x, a.y + c.y, a.z + c.z, a.w + c.w);
    reinterpret_cast<float4*>(g_tmp)[i] = s;
    uint2 hv = make_uint2(pack2(spikef(s.x), spikef(s.y)),
                          pack2(spikef(s.z), spikef(s.w)));
    reinterpret_cast<uint2*>(g_x16)[i] = hv;

    if (i < 4*CC*CC){
        int oc = i >> 8;                               // i*C + o
        float inv = gam[oc] * rsqrtf(var[oc] + 1e-5f);
        float wp = w[i] * inv;
        __half hi = __float2half_rn(wp);
        __half lo = __float2half_rn(wp - __half2float(hi));
        g_w16h[i] = hi;
        g_w16l[i] = lo;
        if (i < 4*CC){
            float invb = gam[i] * rsqrtf(var[i] + 1e-5f);
            g_bp[i] = (b[i] - mean[i]) * invb + beta[i];
        }
    }
}

// ---------------------------------------------------------------------------
// HMMA GEMM with cp.async double-buffered k-chunk pipeline.
// Per CTA: D[m=128, n=128] = sum_k (Whi+Wlo)[m,k] * X[k,n].
// MODE 0: qkv (src g_x16, M=768, out g_qkv fp16 split by branch, spike)
// MODE 1: proj (src g_os,  M=256, out fp32 = D + bias + residual g_tmp)
// ---------------------------------------------------------------------------
#define AS_STRIDE 72                     // halves per A row (144B: 16-aligned, %128=16)
#define BS_STRIDE 136                    // halves per B row (272B)
#define AS_HALVES (2*128*AS_STRIDE)      // 18432 halves (both planes)
#define STG_HALVES (AS_HALVES + 64*BS_STRIDE)   // 27136 halves = 54272 B per stage
#define GEMM_SMEM (2*STG_HALVES*2)       // 108544 B (2 stages)

template<int MODE>
__global__ void __launch_bounds__(256, 2) mma_gemm_kernel(float* __restrict__ out)
{
    extern __shared__ __half smem[];
    const int tid  = threadIdx.x;
    const int wid  = tid >> 5;
    const int lane = tid & 31;
    const int tb = blockIdx.z;
    const int bn = blockIdx.x * 128;
    const int bm = blockIdx.y * 128;
    const int WOFF = (MODE == 0) ? 0 : 768;
    const int wm = (wid & 1) * 64;              // warp m offset
    const int wn = (wid >> 1) * 32;             // warp n offset

    const __half* xsrc   = (MODE == 0 ? g_x16 : g_os) + tb*CN + bn;
    const __half* wsrc_h = g_w16h + (WOFF + bm)*CC;
    const __half* wsrc_l = g_w16l + (WOFF + bm)*CC;

    float acc[16][4];
#pragma unroll
    for (int i = 0; i < 16; i++)
#pragma unroll
        for (int j = 0; j < 4; j++) acc[i][j] = 0.f;

    // ---- async stage issue: A (both planes) + B for k-chunk kt ----
    auto issue = [&](int kt){
        __half* As = smem + (kt & 1)*STG_HALVES;
        __half* Bs = As + AS_HALVES;
        const int k0 = kt * 64;
#pragma unroll
        for (int j = 0; j < 4; j++){
            int idx = tid + 256*j;              // 0..1023
            int r = idx >> 3;                   // m row 0..127
            int c8 = (idx & 7) << 3;            // k offset
            cp_async16(smem_to_u32(&As[r*AS_STRIDE + c8]),        wsrc_h + r*CC + k0 + c8);
            cp_async16(smem_to_u32(&As[(128 + r)*AS_STRIDE + c8]), wsrc_l + r*CC + k0 + c8);
        }
#pragma unroll
        for (int j = 0; j < 4; j++){
            int idx = tid + 256*j;              // 0..1023
            int r = idx >> 4;                   // k row 0..63
            int c8 = (idx & 15) << 3;           // n offset
            cp_async16(smem_to_u32(&Bs[r*BS_STRIDE + c8]), xsrc + (k0 + r)*NN + c8);
        }
        CP_COMMIT();
    };

    issue(0);
    for (int kt = 0; kt < 4; kt++){
        CP_WAIT0();                 // stage kt transfers complete
        __syncthreads();            // visibility + all warps done with stage kt-1 compute
        if (kt < 3) issue(kt + 1);  // overlaps with compute below
        __half* As = smem + (kt & 1)*STG_HALVES;
        __half* Bs = As + AS_HALVES;
#pragma unroll
        for (int kk = 0; kk < 64; kk += 16){
            uint32_t bf[4][2];
#pragma unroll
            for (int nt = 0; nt < 4; nt++){
                uint32_t addr = smem_to_u32(
                    &Bs[(kk + (lane & 15))*BS_STRIDE + wn + nt*8]);
                ldsm_x2_trans(bf[nt], addr);
            }
#pragma unroll
            for (int mt = 0; mt < 4; mt++){
#pragma unroll
                for (int p = 0; p < 2; p++){
                    uint32_t af[4];
                    uint32_t addr = smem_to_u32(
                        &As[(p*128 + wm + mt*16 + (lane & 15))*AS_STRIDE
                            + kk + (lane >> 4)*8]);
                    ldsm_x4(af, addr);
#pragma unroll
                    for (int nt = 0; nt < 4; nt++)
                        mma16816(acc[mt*4 + nt], af, bf[nt]);
                }
            }
        }
    }

    // ---- epilogue ----
#pragma unroll
    for (int mt = 0; mt < 4; mt++){
#pragma unroll
        for (int nt = 0; nt < 4; nt++){
            const float* a = acc[mt*4 + nt];
            int row = wm + mt*16 + (lane >> 2);      // 0..127 (and +8)
            int col = wn + nt*8 + ((lane & 3) << 1); // 0..126, even
            if (MODE == 0){
                int gm0 = bm + row, gm1 = gm0 + 8;
                float b0 = g_bp[gm0], b1 = g_bp[gm1];
                uint32_t v0 = pack2(spikef(a[0] + b0), spikef(a[1] + b0));
                uint32_t v1 = pack2(spikef(a[2] + b1), spikef(a[3] + b1));
                *reinterpret_cast<uint32_t*>(
                    &g_qkv[(gm0 >> 8)*TBCN + tb*CN + (gm0 & 255)*NN + bn + col]) = v0;
                *reinterpret_cast<uint32_t*>(
                    &g_qkv[(gm1 >> 8)*TBCN + tb*CN + (gm1 & 255)*NN + bn + col]) = v1;
            } else {
                int gm0 = bm + row, gm1 = gm0 + 8;
                float b0 = g_bp[768 + gm0], b1 = g_bp[768 + gm1];
                int i0 = tb*CN + gm0*NN + bn + col;
                int i1 = tb*CN + gm1*NN + bn + col;
                float2 r0 = *reinterpret_cast<const float2*>(&g_tmp[i0]);
                float2 r1 = *reinterpret_cast<const float2*>(&g_tmp[i1]);
                float2 v0 = make_float2(a[0] + b0 + r0.x, a[1] + b0 + r0.y);
                float2 v1 = make_float2(a[2] + b1 + r1.x, a[3] + b1 + r1.y);
                *reinterpret_cast<float2*>(&out[i0]) = v0;
                *reinterpret_cast<float2*>(&out[i1]) = v1;
            }
        }
    }
}

// ---------------------------------------------------------------------------
// Attention phase 1 (HMMA, n-split): partial M[e,d] over one 128-n chunk.
// grid 512 = 64 heads x 8 chunks. Cross-warp smem reduce, then PLAIN fp16
// stores into g_Mp[hh][chunk] — exact (partials are multiples of 1/16, <=128,
// ulp(fp16)@[64,128) = 1/16). No atomics.
// ---------------------------------------------------------------------------
#define KV_STRIDE 136
__global__ void __launch_bounds__(256) kv_kernel()
{
    __shared__ __align__(16) char sbuf[32768];
    __half (*Ks)[KV_STRIDE] = reinterpret_cast<__half(*)[KV_STRIDE]>(sbuf);
    __half (*Vs)[KV_STRIDE] = reinterpret_cast<__half(*)[KV_STRIDE]>(sbuf + 32*KV_STRIDE*2);
    float (*red)[1024] = reinterpret_cast<float(*)[1024]>(sbuf);   // aliases Ks/Vs

    const int hh = blockIdx.x >> 3;              // 0..63
    const int ch = blockIdx.x & 7;               // chunk 0..7
    const int nb = ch << 7;                      // n chunk base
    const int tid = threadIdx.x;
    const int wid = tid >> 5;
    const int lane = tid & 31;
    const __half* K = g_qkv + TBCN   + hh*DD*NN;
    const __half* V = g_qkv + 2*TBCN + hh*DD*NN;

    // load K,V 32 x 128 chunk
#pragma unroll
    for (int j = 0; j < 2; j++){
        int idx = tid + 256*j;                   // 0..511
        int r = idx >> 4;                        // row 0..31
        int c8 = (idx & 15) << 3;                // 0..120
        *reinterpret_cast<uint4*>(&Ks[r][c8]) =
            *reinterpret_cast<const uint4*>(&K[r*NN + nb + c8]);
        *reinterpret_cast<uint4*>(&Vs[r][c8]) =
            *reinterpret_cast<const uint4*>(&V[r*NN + nb + c8]);
    }
    __syncthreads();

    float acc[2][4][4];
#pragma unroll
    for (int mt = 0; mt < 2; mt++)
#pragma unroll
        for (int nt = 0; nt < 4; nt++)
#pragma unroll
            for (int i = 0; i < 4; i++) acc[mt][nt][i] = 0.f;

    const int kslice = wid * 16;
    uint32_t a0[4], a1[4];
    ldsm_x4(a0, smem_to_u32(&Ks[lane & 15][kslice + (lane >> 4)*8]));
    ldsm_x4(a1, smem_to_u32(&Ks[16 + (lane & 15)][kslice + (lane >> 4)*8]));
#pragma unroll
    for (int nt = 0; nt < 4; nt++){
        uint32_t bf[2];
        ldsm_x2(bf, smem_to_u32(&Vs[nt*8 + (lane & 7)][kslice + ((lane >> 3) & 1)*8]));
        mma16816(acc[0][nt], a0, bf);
        mma16816(acc[1][nt], a1, bf);
    }
    __syncthreads();

    // ---- cross-warp reduction (red aliases Ks/Vs) ----
#pragma unroll
    for (int mt = 0; mt < 2; mt++)
#pragma unroll
        for (int nt = 0; nt < 4; nt++)
#pragma unroll
            for (int i = 0; i < 4; i++){
                int e = mt*16 + (lane >> 2) + ((i >= 2) ? 8 : 0);
                int d = nt*8 + ((lane & 3) << 1) + (i & 1);
                red[wid][e*32 + d] = acc[mt][nt][i];
            }
    __syncthreads();
    // 1024 sums, 4 per thread, coalesced; exact fp16 partial store
#pragma unroll
    for (int i = 0; i < 4; i++){
        int j = tid + i*256;                     // covers 0..1023, all indices
        float s = red[0][j] + red[1][j] + red[2][j] + red[3][j]
                + red[4][j] + red[5][j] + red[6][j] + red[7][j];
        g_Mp[(hh*8 + ch)*1024 + j] = __float2half_rn(s);    // exact
    }
}

// ---------------------------------------------------------------------------
// M reduce: per head, sum the 8 fp16 chunk partials (exact in fp32), split
// into exact fp16 hi/lo, store TRANSPOSED [d][e]. grid 64 x 256.
// COALESCED both ways via padded smem transpose (R15's version read with a
// 64B stride -> 32 transactions/warp; this one is fully coalesced).
// ---------------------------------------------------------------------------
__global__ void __launch_bounds__(256) mreduce_kernel()
{
    __shared__ float s[32][33];                  // [e][d], pad -> conflict-free
    const int hh = blockIdx.x;
    const int tid = threadIdx.x;
    // phase 1: coalesced reads in j = e*32+d order, sum 8 planes
#pragma unroll
    for (int i = 0; i < 4; i++){
        int j = tid + i*256;                     // 0..1023
        const __half* mp = g_Mp + hh*8192 + j;
        float v = 0.f;
#pragma unroll
        for (int c = 0; c < 8; c++) v += __half2float(mp[c*1024]);
        s[j >> 5][j & 31] = v;
    }
    __syncthreads();
    // phase 2: write hi/lo coalesced in o = d*32+e order
#pragma unroll
    for (int i = 0; i < 4; i++){
        int o = tid + i*256;                     // 0..1023
        int d = o >> 5, e = o & 31;
        float v = s[e][d];                       // stride-33 rows: conflict-free
        __half hi = __float2half_rn(v);
        g_Mh[hh*1024 + o] = hi;
        g_Ml[hh*1024 + o] = __float2half_rn(v - __half2float(hi));
    }
}

// ---------------------------------------------------------------------------
// Attention phase 2 (HMMA, n-split): O[d,n] = spike(0.1*sum_e M[e,d]*Q[e,n]).
// grid 512 = 64 heads x 8 x 128-n chunks. Mh/Ml preloaded from mreduce.
// A = M^T hi/lo, B = Q (trans ldsm). 8 warps x 16-n windows.
// ---------------------------------------------------------------------------
#define QS_STRIDE 136
__global__ void __launch_bounds__(256) qm_kernel()
{
    __shared__ __align__(16) __half Qs[32][QS_STRIDE];
    __shared__ __align__(16) __half Mh[32][40];
    __shared__ __align__(16) __half Ml[32][40];
    const int hh = blockIdx.x >> 3;
    const int nb = (blockIdx.x & 7) << 7;        // 128-n chunk base
    const int tid = threadIdx.x;
    const int wid = tid >> 5;
    const int lane = tid & 31;
    const int cbase = hh * (DD*NN);
    const __half* Q = g_qkv + cbase;

    // copy reduced hi/lo M^T tiles ([d][e] layout already; coalesced)
#pragma unroll
    for (int i = tid; i < 1024; i += 256){
        int d = i >> 5, e = i & 31;
        Mh[d][e] = g_Mh[hh*1024 + i];
        Ml[d][e] = g_Ml[hh*1024 + i];
    }
    // load Q chunk [32 e][128 n]
#pragma unroll
    for (int j = 0; j < 2; j++){
        int idx = tid + 256*j;                   // 0..511
        int r = idx >> 4;                        // e row 0..31
        int c8 = (idx & 15) << 3;                // 0..120
        *reinterpret_cast<uint4*>(&Qs[r][c8]) =
            *reinterpret_cast<const uint4*>(&Q[r*NN + nb + c8]);
    }
    __syncthreads();

    const int wn = wid * 16;
    float acc[2][2][4];
#pragma unroll
    for (int mt = 0; mt < 2; mt++)
#pragma unroll
        for (int nt = 0; nt < 2; nt++)
#pragma unroll
            for (int i = 0; i < 4; i++) acc[mt][nt][i] = 0.f;

#pragma unroll
    for (int e0 = 0; e0 < 32; e0 += 16){
        uint32_t bf[2][2];
#pragma unroll
        for (int nt = 0; nt < 2; nt++)
            ldsm_x2_trans(bf[nt],
                smem_to_u32(&Qs[e0 + (lane & 15)][wn + nt*8]));
#pragma unroll
        for (int mt = 0; mt < 2; mt++){
            uint32_t ah[4], al[4];
            ldsm_x4(ah, smem_to_u32(&Mh[mt*16 + (lane & 15)][e0 + (lane >> 4)*8]));
            ldsm_x4(al, smem_to_u32(&Ml[mt*16 + (lane & 15)][e0 + (lane >> 4)*8]));
#pragma unroll
            for (int nt = 0; nt < 2; nt++){
                mma16816(acc[mt][nt], ah, bf[nt]);
                mma16816(acc[mt][nt], al, bf[nt]);
            }
        }
    }

    // epilogue: spike(0.1*O) -> g_os fp16
#pragma unroll
    for (int mt = 0; mt < 2; mt++){
#pragma unroll
        for (int nt = 0; nt < 2; nt++){
            const float* a = acc[mt][nt];
            int d0 = mt*16 + (lane >> 2);
            int n  = nb + wn + nt*8 + ((lane & 3) << 1);
            uint32_t v0 = pack2(spikef(0.1f*a[0]), spikef(0.1f*a[1]));
            uint32_t v1 = pack2(spikef(0.1f*a[2]), spikef(0.1f*a[3]));
            *reinterpret_cast<uint32_t*>(&g_os[cbase + d0*NN + n]) = v0;
            *reinterpret_cast<uint32_t*>(&g_os[cbase + (d0+8)*NN + n]) = v1;
        }
    }
}

// ---------------------------------------------------------------------------
extern "C" void kernel_launch(void* const* d_in, const int* in_sizes, int n_in,
                              void* d_out, int out_size)
{
    const float* q    = (const float*)d_in[0];
    // d_in[1] (key) and d_in[2] (value) are unused by the reference
    const float* qp   = (const float*)d_in[3];
    const float* w    = (const float*)d_in[4];
    const float* b    = (const float*)d_in[5];
    const float* gam  = (const float*)d_in[6];
    const float* bet  = (const float*)d_in[7];
    const float* mean = (const float*)d_in[8];
    const float* var  = (const float*)d_in[9];
    float* out = (float*)d_out;

    cudaFuncSetAttribute(mma_gemm_kernel<0>,
                         cudaFuncAttributeMaxDynamicSharedMemorySize, GEMM_SMEM);
    cudaFuncSetAttribute(mma_gemm_kernel<1>,
                         cudaFuncAttributeMaxDynamicSharedMemorySize, GEMM_SMEM);

    prep_kernel<<<(TBCN/4)/256, 256>>>((const float4*)q, (const float4*)qp,
                                       w, b, gam, bet, mean, var);

    dim3 gq(NN/128, 768/128, TB);   // 8 x 6 x 8 = 384 CTAs
    mma_gemm_kernel<0><<<gq, 256, GEMM_SMEM>>>(nullptr);

    kv_kernel<<<512, 256>>>();
    mreduce_kernel<<<64, 256>>>();
    qm_kernel<<<512, 256>>>();

    dim3 gp(NN/128, CC/128, TB);    // 8 x 2 x 8 = 128 CTAs
    mma_gemm_kernel<1><<<gp, 256, GEMM_SMEM>>>(out);
}

// round 17
// speedup vs baseline: 1.0308x; 1.0185x over previous
#include <cuda_runtime.h>
#include <cuda_fp16.h>
#include <math.h>
#include <cstdint>

#define TT 4
#define BB 2
#define TB 8
#define NN 1024
#define CC 256
#define HH 8
#define DD 32
#define CN (CC*NN)        // 262144
#define TBCN (TB*CN)      // 2097152

// ---------------------------------------------------------------------------
// Scratch (static device globals: no allocations allowed)
// ---------------------------------------------------------------------------
__device__ float g_tmp[TBCN];                        // query + query_pos (fp32, residual)
__device__ __align__(16) __half g_x16[TBCN];         // spike(tmp) fp16 (qkv GEMM input)
__device__ __align__(16) __half g_qkv[3*TBCN];       // spiked q,k,v fp16 (TB,C,N)
__device__ __align__(16) __half g_os[TBCN];          // spiked attention output fp16
__device__ __align__(16) __half g_Mp[64*8*1024];     // per-(head,chunk) K^T V partials fp16 (exact)
__device__ __align__(16) __half g_Mh[64*1024];       // reduced M hi fp16, [head][e][d] (j order)
__device__ __align__(16) __half g_Ml[64*1024];       // reduced M lo fp16, [head][e][d] (j order)
__device__ __align__(16) __half g_w16h[4*CC*CC];     // BN-folded weights hi
__device__ __align__(16) __half g_w16l[4*CC*CC];     // BN-folded weights lo
__device__ float g_bp[4*CC];                         // BN-folded biases

// MultiSpike_norm4: round(clamp(x,0,4))/4 ; jnp.round = round-half-even = rintf
__device__ __forceinline__ float spikef(float v){
    v = fminf(fmaxf(v, 0.0f), 4.0f);
    return rintf(v) * 0.25f;
}

__device__ __forceinline__ uint32_t pack2(float a, float b){
    __half2 h = __halves2half2(__float2half_rn(a), __float2half_rn(b));
    return *reinterpret_cast<uint32_t*>(&h);
}

__device__ __forceinline__ uint32_t smem_to_u32(const void* p) {
    uint32_t a;
    asm("{ .reg .u64 t; cvta.to.shared.u64 t, %1; cvt.u32.u64 %0, t; }"
        : "=r"(a) : "l"(p));
    return a;
}

// ---------------------------------------------------------------------------
// Warp MMA + async-copy primitives (baseline PTX, works on .target sm_100)
// ---------------------------------------------------------------------------
__device__ __forceinline__ void ldsm_x4(uint32_t* a, uint32_t addr){
    asm volatile("ldmatrix.sync.aligned.m8n8.x4.shared.b16 {%0,%1,%2,%3}, [%4];"
        : "=r"(a[0]),"=r"(a[1]),"=r"(a[2]),"=r"(a[3]) : "r"(addr));
}
__device__ __forceinline__ void ldsm_x2(uint32_t* b, uint32_t addr){
    asm volatile("ldmatrix.sync.aligned.m8n8.x2.shared.b16 {%0,%1}, [%2];"
        : "=r"(b[0]),"=r"(b[1]) : "r"(addr));
}
__device__ __forceinline__ void ldsm_x2_trans(uint32_t* b, uint32_t addr){
    asm volatile("ldmatrix.sync.aligned.m8n8.x2.trans.shared.b16 {%0,%1}, [%2];"
        : "=r"(b[0]),"=r"(b[1]) : "r"(addr));
}
__device__ __forceinline__ void mma16816(float* d, const uint32_t* a, const uint32_t* b){
    asm volatile("mma.sync.aligned.m16n8k16.row.col.f32.f16.f16.f32 "
        "{%0,%1,%2,%3}, {%4,%5,%6,%7}, {%8,%9}, {%0,%1,%2,%3};"
        : "+f"(d[0]),"+f"(d[1]),"+f"(d[2]),"+f"(d[3])
        : "r"(a[0]),"r"(a[1]),"r"(a[2]),"r"(a[3]), "r"(b[0]),"r"(b[1]));
}
__device__ __forceinline__ void cp_async16(uint32_t smem_addr, const void* gptr){
    asm volatile("cp.async.cg.shared.global [%0], [%1], 16;"
        :: "r"(smem_addr), "l"(gptr));
}
#define CP_COMMIT() asm volatile("cp.async.commit_group;" ::: "memory")
#define CP_WAIT0()  asm volatile("cp.async.wait_group 0;"  ::: "memory")

// ---------------------------------------------------------------------------
// prep (+ merged weight fold):
//   all 2048 CTAs: tmp = q + qp (fp32); x16 = spike(tmp) fp16.
//   CTAs 0..1023 additionally fold one weight element per thread.
// ---------------------------------------------------------------------------
__global__ void prep_kernel(const float4* __restrict__ q, const float4* __restrict__ qp,
                            const float* __restrict__ w,
                            const float* __restrict__ b,
                            const float* __restrict__ gam,
                            const float* __restrict__ beta,
                            const float* __restrict__ mean,
                            const float* __restrict__ var)
{
    int i = blockIdx.x * blockDim.x + threadIdx.x;     // TBCN/4 threads
    float4 a = q[i], c = qp[i];
    float4 s = make_float4(a.x + c.x, a.y + c.y, a.z + c.z, a.w + c.w);
    reinterpret_cast<float4*>(g_tmp)[i] = s;
    uint2 hv = make_uint2(pack2(spikef(s.x), spikef(s.y)),
                          pack2(spikef(s.z), spikef(s.w)));
    reinterpret_cast<uint2*>(g_x16)[i] = hv;

    if (i < 4*CC*CC){
        int oc = i >> 8;                               // i*C + o
        float inv = gam[oc] * rsqrtf(var[oc] + 1e-5f);
        float wp = w[i] * inv;
        __half hi = __float2half_rn(wp);
        __half lo = __float2half_rn(wp - __half2float(hi));
        g_w16h[i] = hi;
        g_w16l[i] = lo;
        if (i < 4*CC){
            float invb = gam[i] * rsqrtf(var[i] + 1e-5f);
            g_bp[i] = (b[i] - mean[i]) * invb + beta[i];
        }
    }
}

// ---------------------------------------------------------------------------
// HMMA GEMM with cp.async double-buffered k-chunk pipeline.
// Per CTA: D[m=128, n=128] = sum_k (Whi+Wlo)[m,k] * X[k,n].
// MODE 0: qkv (src g_x16, M=768, out g_qkv fp16 split by branch, spike)
// MODE 1: proj (src g_os,  M=256, out fp32 = D + bias + residual g_tmp)
// ---------------------------------------------------------------------------
#define AS_STRIDE 72                     // halves per A row (144B: 16-aligned, %128=16)
#define BS_STRIDE 136                    // halves per B row (272B)
#define AS_HALVES (2*128*AS_STRIDE)      // 18432 halves (both planes)
#define STG_HALVES (AS_HALVES + 64*BS_STRIDE)   // 27136 halves = 54272 B per stage
#define GEMM_SMEM (2*STG_HALVES*2)       // 108544 B (2 stages)

template<int MODE>
__global__ void __launch_bounds__(256, 2) mma_gemm_kernel(float* __restrict__ out)
{
    extern __shared__ __half smem[];
    const int tid  = threadIdx.x;
    const int wid  = tid >> 5;
    const int lane = tid & 31;
    const int tb = blockIdx.z;
    const int bn = blockIdx.x * 128;
    const int bm = blockIdx.y * 128;
    const int WOFF = (MODE == 0) ? 0 : 768;
    const int wm = (wid & 1) * 64;              // warp m offset
    const int wn = (wid >> 1) * 32;             // warp n offset

    const __half* xsrc   = (MODE == 0 ? g_x16 : g_os) + tb*CN + bn;
    const __half* wsrc_h = g_w16h + (WOFF + bm)*CC;
    const __half* wsrc_l = g_w16l + (WOFF + bm)*CC;

    float acc[16][4];
#pragma unroll
    for (int i = 0; i < 16; i++)
#pragma unroll
        for (int j = 0; j < 4; j++) acc[i][j] = 0.f;

    // ---- async stage issue: A (both planes) + B for k-chunk kt ----
    auto issue = [&](int kt){
        __half* As = smem + (kt & 1)*STG_HALVES;
        __half* Bs = As + AS_HALVES;
        const int k0 = kt * 64;
#pragma unroll
        for (int j = 0; j < 4; j++){
            int idx = tid + 256*j;              // 0..1023
            int r = idx >> 3;                   // m row 0..127
            int c8 = (idx & 7) << 3;            // k offset
            cp_async16(smem_to_u32(&As[r*AS_STRIDE + c8]),        wsrc_h + r*CC + k0 + c8);
            cp_async16(smem_to_u32(&As[(128 + r)*AS_STRIDE + c8]), wsrc_l + r*CC + k0 + c8);
        }
#pragma unroll
        for (int j = 0; j < 4; j++){
            int idx = tid + 256*j;              // 0..1023
            int r = idx >> 4;                   // k row 0..63
            int c8 = (idx & 15) << 3;           // n offset
            cp_async16(smem_to_u32(&Bs[r*BS_STRIDE + c8]), xsrc + (k0 + r)*NN + c8);
        }
        CP_COMMIT();
    };

    issue(0);
    for (int kt = 0; kt < 4; kt++){
        CP_WAIT0();                 // stage kt transfers complete
        __syncthreads();            // visibility + all warps done with stage kt-1 compute
        if (kt < 3) issue(kt + 1);  // overlaps with compute below
        __half* As = smem + (kt & 1)*STG_HALVES;
        __half* Bs = As + AS_HALVES;
#pragma unroll
        for (int kk = 0; kk < 64; kk += 16){
            uint32_t bf[4][2];
#pragma unroll
            for (int nt = 0; nt < 4; nt++){
                uint32_t addr = smem_to_u32(
                    &Bs[(kk + (lane & 15))*BS_STRIDE + wn + nt*8]);
                ldsm_x2_trans(bf[nt], addr);
            }
#pragma unroll
            for (int mt = 0; mt < 4; mt++){
#pragma unroll
                for (int p = 0; p < 2; p++){
                    uint32_t af[4];
                    uint32_t addr = smem_to_u32(
                        &As[(p*128 + wm + mt*16 + (lane & 15))*AS_STRIDE
                            + kk + (lane >> 4)*8]);
                    ldsm_x4(af, addr);
#pragma unroll
                    for (int nt = 0; nt < 4; nt++)
                        mma16816(acc[mt*4 + nt], af, bf[nt]);
                }
            }
        }
    }

    // ---- epilogue ----
#pragma unroll
    for (int mt = 0; mt < 4; mt++){
#pragma unroll
        for (int nt = 0; nt < 4; nt++){
            const float* a = acc[mt*4 + nt];
            int row = wm + mt*16 + (lane >> 2);      // 0..127 (and +8)
            int col = wn + nt*8 + ((lane & 3) << 1); // 0..126, even
            if (MODE == 0){
                int gm0 = bm + row, gm1 = gm0 + 8;
                float b0 = g_bp[gm0], b1 = g_bp[gm1];
                uint32_t v0 = pack2(spikef(a[0] + b0), spikef(a[1] + b0));
                uint32_t v1 = pack2(spikef(a[2] + b1), spikef(a[3] + b1));
                *reinterpret_cast<uint32_t*>(
                    &g_qkv[(gm0 >> 8)*TBCN + tb*CN + (gm0 & 255)*NN + bn + col]) = v0;
                *reinterpret_cast<uint32_t*>(
                    &g_qkv[(gm1 >> 8)*TBCN + tb*CN + (gm1 & 255)*NN + bn + col]) = v1;
            } else {
                int gm0 = bm + row, gm1 = gm0 + 8;
                float b0 = g_bp[768 + gm0], b1 = g_bp[768 + gm1];
                int i0 = tb*CN + gm0*NN + bn + col;
                int i1 = tb*CN + gm1*NN + bn + col;
                float2 r0 = *reinterpret_cast<const float2*>(&g_tmp[i0]);
                float2 r1 = *reinterpret_cast<const float2*>(&g_tmp[i1]);
                float2 v0 = make_float2(a[0] + b0 + r0.x, a[1] + b0 + r0.y);
                float2 v1 = make_float2(a[2] + b1 + r1.x, a[3] + b1 + r1.y);
                *reinterpret_cast<float2*>(&out[i0]) = v0;
                *reinterpret_cast<float2*>(&out[i1]) = v1;
            }
        }
    }
}

// ---------------------------------------------------------------------------
// Attention phase 1 (HMMA, n-split): partial M[e,d] over one 128-n chunk.
// grid 512 = 64 heads x 8 chunks. Cross-warp smem reduce, then PLAIN fp16
// stores into g_Mp[hh][chunk] — exact (partials are multiples of 1/16, <=128,
// ulp(fp16)@[64,128) = 1/16). No atomics.
// ---------------------------------------------------------------------------
#define KV_STRIDE 136
__global__ void __launch_bounds__(256) kv_kernel()
{
    __shared__ __align__(16) char sbuf[32768];
    __half (*Ks)[KV_STRIDE] = reinterpret_cast<__half(*)[KV_STRIDE]>(sbuf);
    __half (*Vs)[KV_STRIDE] = reinterpret_cast<__half(*)[KV_STRIDE]>(sbuf + 32*KV_STRIDE*2);
    float (*red)[1024] = reinterpret_cast<float(*)[1024]>(sbuf);   // aliases Ks/Vs

    const int hh = blockIdx.x >> 3;              // 0..63
    const int ch = blockIdx.x & 7;               // chunk 0..7
    const int nb = ch << 7;                      // n chunk base
    const int tid = threadIdx.x;
    const int wid = tid >> 5;
    const int lane = tid & 31;
    const __half* K = g_qkv + TBCN   + hh*DD*NN;
    const __half* V = g_qkv + 2*TBCN + hh*DD*NN;

    // load K,V 32 x 128 chunk
#pragma unroll
    for (int j = 0; j < 2; j++){
        int idx = tid + 256*j;                   // 0..511
        int r = idx >> 4;                        // row 0..31
        int c8 = (idx & 15) << 3;                // 0..120
        *reinterpret_cast<uint4*>(&Ks[r][c8]) =
            *reinterpret_cast<const uint4*>(&K[r*NN + nb + c8]);
        *reinterpret_cast<uint4*>(&Vs[r][c8]) =
            *reinterpret_cast<const uint4*>(&V[r*NN + nb + c8]);
    }
    __syncthreads();

    float acc[2][4][4];
#pragma unroll
    for (int mt = 0; mt < 2; mt++)
#pragma unroll
        for (int nt = 0; nt < 4; nt++)
#pragma unroll
            for (int i = 0; i < 4; i++) acc[mt][nt][i] = 0.f;

    const int kslice = wid * 16;
    uint32_t a0[4], a1[4];
    ldsm_x4(a0, smem_to_u32(&Ks[lane & 15][kslice + (lane >> 4)*8]));
    ldsm_x4(a1, smem_to_u32(&Ks[16 + (lane & 15)][kslice + (lane >> 4)*8]));
#pragma unroll
    for (int nt = 0; nt < 4; nt++){
        uint32_t bf[2];
        ldsm_x2(bf, smem_to_u32(&Vs[nt*8 + (lane & 7)][kslice + ((lane >> 3) & 1)*8]));
        mma16816(acc[0][nt], a0, bf);
        mma16816(acc[1][nt], a1, bf);
    }
    __syncthreads();

    // ---- cross-warp reduction (red aliases Ks/Vs) ----
#pragma unroll
    for (int mt = 0; mt < 2; mt++)
#pragma unroll
        for (int nt = 0; nt < 4; nt++)
#pragma unroll
            for (int i = 0; i < 4; i++){
                int e = mt*16 + (lane >> 2) + ((i >= 2) ? 8 : 0);
                int d = nt*8 + ((lane & 3) << 1) + (i & 1);
                red[wid][e*32 + d] = acc[mt][nt][i];
            }
    __syncthreads();
    // 1024 sums, 4 per thread, coalesced; exact fp16 partial store
#pragma unroll
    for (int i = 0; i < 4; i++){
        int j = tid + i*256;                     // covers 0..1023, all indices
        float s = red[0][j] + red[1][j] + red[2][j] + red[3][j]
                + red[4][j] + red[5][j] + red[6][j] + red[7][j];
        g_Mp[(hh*8 + ch)*1024 + j] = __float2half_rn(s);    // exact
    }
}

// ---------------------------------------------------------------------------
// M reduce: sum the 8 fp16 chunk partials (exact in fp32), split into exact
// fp16 hi/lo, store in NATURAL [e][d] (j) order — fully coalesced, no smem.
// grid 256 = 64 heads x 4 j-chunks, 1 output/thread. (Transpose now happens
// in qm's smem prologue where it's free.)
// ---------------------------------------------------------------------------
__global__ void __launch_bounds__(256) mreduce_kernel()
{
    const int hh = blockIdx.x >> 2;
    const int j  = ((blockIdx.x & 3) << 8) + threadIdx.x;   // 0..1023
    const __half* mp = g_Mp + hh*8192 + j;
    float v = 0.f;
#pragma unroll
    for (int c = 0; c < 8; c++) v += __half2float(mp[c*1024]);
    __half hi = __float2half_rn(v);
    g_Mh[hh*1024 + j] = hi;
    g_Ml[hh*1024 + j] = __float2half_rn(v - __half2float(hi));
}

// ---------------------------------------------------------------------------
// Attention phase 2 (HMMA, n-split): O[d,n] = spike(0.1*sum_e M[e,d]*Q[e,n]).
// grid 512 = 64 heads x 8 x 128-n chunks. g_Mh/g_Ml are [e][d]; coalesced
// global reads + smem-side transpose into padded [d][e] tiles.
// A = M^T hi/lo, B = Q (trans ldsm). 8 warps x 16-n windows.
// ---------------------------------------------------------------------------
#define QS_STRIDE 136
__global__ void __launch_bounds__(256) qm_kernel()
{
    __shared__ __align__(16) __half Qs[32][QS_STRIDE];
    __shared__ __align__(16) __half Mh[32][40];
    __shared__ __align__(16) __half Ml[32][40];
    const int hh = blockIdx.x >> 3;
    const int nb = (blockIdx.x & 7) << 7;        // 128-n chunk base
    const int tid = threadIdx.x;
    const int wid = tid >> 5;
    const int lane = tid & 31;
    const int cbase = hh * (DD*NN);
    const __half* Q = g_qkv + cbase;

    // coalesced [e][d]-order reads; transpose into smem [d][e] tiles
#pragma unroll
    for (int i = tid; i < 1024; i += 256){
        int e = i >> 5, d = i & 31;
        Mh[d][e] = g_Mh[hh*1024 + i];
        Ml[d][e] = g_Ml[hh*1024 + i];
    }
    // load Q chunk [32 e][128 n]
#pragma unroll
    for (int j = 0; j < 2; j++){
        int idx = tid + 256*j;                   // 0..511
        int r = idx >> 4;                        // e row 0..31
        int c8 = (idx & 15) << 3;                // 0..120
        *reinterpret_cast<uint4*>(&Qs[r][c8]) =
            *reinterpret_cast<const uint4*>(&Q[r*NN + nb + c8]);
    }
    __syncthreads();

    const int wn = wid * 16;
    float acc[2][2][4];
#pragma unroll
    for (int mt = 0; mt < 2; mt++)
#pragma unroll
        for (int nt = 0; nt < 2; nt++)
#pragma unroll
            for (int i = 0; i < 4; i++) acc[mt][nt][i] = 0.f;

#pragma unroll
    for (int e0 = 0; e0 < 32; e0 += 16){
        uint32_t bf[2][2];
#pragma unroll
        for (int nt = 0; nt < 2; nt++)
            ldsm_x2_trans(bf[nt],
                smem_to_u32(&Qs[e0 + (lane & 15)][wn + nt*8]));
#pragma unroll
        for (int mt = 0; mt < 2; mt++){
            uint32_t ah[4], al[4];
            ldsm_x4(ah, smem_to_u32(&Mh[mt*16 + (lane & 15)][e0 + (lane >> 4)*8]));
            ldsm_x4(al, smem_to_u32(&Ml[mt*16 + (lane & 15)][e0 + (lane >> 4)*8]));
#pragma unroll
            for (int nt = 0; nt < 2; nt++){
                mma16816(acc[mt][nt], ah, bf[nt]);
                mma16816(acc[mt][nt], al, bf[nt]);
            }
        }
    }

    // epilogue: spike(0.1*O) -> g_os fp16
#pragma unroll
    for (int mt = 0; mt < 2; mt++){
#pragma unroll
        for (int nt = 0; nt < 2; nt++){
            const float* a = acc[mt][nt];
            int d0 = mt*16 + (lane >> 2);
            int n  = nb + wn + nt*8 + ((lane & 3) << 1);
            uint32_t v0 = pack2(spikef(0.1f*a[0]), spikef(0.1f*a[1]));
            uint32_t v1 = pack2(spikef(0.1f*a[2]), spikef(0.1f*a[3]));
            *reinterpret_cast<uint32_t*>(&g_os[cbase + d0*NN + n]) = v0;
            *reinterpret_cast<uint32_t*>(&g_os[cbase + (d0+8)*NN + n]) = v1;
        }
    }
}

// ---------------------------------------------------------------------------
extern "C" void kernel_launch(void* const* d_in, const int* in_sizes, int n_in,
                              void* d_out, int out_size)
{
    const float* q    = (const float*)d_in[0];
    // d_in[1] (key) and d_in[2] (value) are unused by the reference
    const float* qp   = (const float*)d_in[3];
    const float* w    = (const float*)d_in[4];
    const float* b    = (const float*)d_in[5];
    const float* gam  = (const float*)d_in[6];
    const float* bet  = (const float*)d_in[7];
    const float* mean = (const float*)d_in[8];
    const float* var  = (const float*)d_in[9];
    float* out = (float*)d_out;

    cudaFuncSetAttribute(mma_gemm_kernel<0>,
                         cudaFuncAttributeMaxDynamicSharedMemorySize, GEMM_SMEM);
    cudaFuncSetAttribute(mma_gemm_kernel<1>,
                         cudaFuncAttributeMaxDynamicSharedMemorySize, GEMM_SMEM);

    prep_kernel<<<(TBCN/4)/256, 256>>>((const float4*)q, (const float4*)qp,
                                       w, b, gam, bet, mean, var);

    dim3 gq(NN/128, 768/128, TB);   // 8 x 6 x 8 = 384 CTAs
    mma_gemm_kernel<0><<<gq, 256, GEMM_SMEM>>>(nullptr);

    kv_kernel<<<512, 256>>>();
    mreduce_kernel<<<256, 256>>>();
    qm_kernel<<<512, 256>>>();

    dim3 gp(NN/128, CC/128, TB);    // 8 x 2 x 8 = 128 CTAs
    mma_gemm_kernel<1><<<gp, 256, GEMM_SMEM>>>(out);
}